// round 5
// baseline (speedup 1.0000x reference)
#include <cuda_runtime.h>
#include <math.h>

#define NN 100000
#define EE 1600000

// ---------------- static device scratch (no allocation allowed) ----------------
__device__ float4   g_h4[NN * 16];    // per-layer transformed features (row stride C floats)
__device__ float4   g_a4[NN * 16];    // aggregation output (next layer input, pre-bias)
__device__ float4   g_als4[NN];       // attention logits (src side), one float4 = 4 heads
__device__ float4   g_ald4[NN];       // attention logits (dst side)
__device__ int      g_rowptr[NN + 1];
__device__ int      g_cursor[NN];
__device__ int      g_col[EE];
__device__ int      g_bsum[512];
__device__ unsigned g_gmax[16];       // per-layer (4) x per-head (4) global max of als, order-encoded
__device__ float    g_pool[64 * 8];
__device__ float    g_cnt[64];

// order-preserving float<->uint encoding (works across signs)
__device__ __forceinline__ unsigned f2u_ord(float x) {
    unsigned s = __float_as_uint(x);
    return (s & 0x80000000u) ? ~s : (s | 0x80000000u);
}
__device__ __forceinline__ float u2f_ord(unsigned u) {
    unsigned s = (u & 0x80000000u) ? (u ^ 0x80000000u) : ~u;
    return __uint_as_float(s);
}

// ---------------- CSR build ----------------
__global__ void k_zero_cursor() {
    int i = blockIdx.x * 256 + threadIdx.x;
    if (i < NN) g_cursor[i] = 0;
    if (blockIdx.x == 0 && threadIdx.x < 16) g_gmax[threadIdx.x] = 0u;  // below any real encoding
}

// edge_index / batch are int32 (JAX x64-disabled downgrades the requested int64)
__global__ void k_count(const int* __restrict__ ei) {
    int e = blockIdx.x * 256 + threadIdx.x;
    if (e < EE) atomicAdd(&g_cursor[ei[EE + e]], 1);
}

__global__ void k_scan1() {
    __shared__ int sm[256];
    int t = threadIdx.x;
    int i = blockIdx.x * 256 + t;
    int v = (i < NN) ? g_cursor[i] : 0;
    sm[t] = v;
    __syncthreads();
    for (int d = 1; d < 256; d <<= 1) {
        int x = (t >= d) ? sm[t - d] : 0;
        __syncthreads();
        sm[t] += x;
        __syncthreads();
    }
    if (i < NN) g_rowptr[i] = sm[t] - v;   // block-local exclusive
    if (t == 255) g_bsum[blockIdx.x] = sm[255];
}

__global__ void k_scan2() {
    __shared__ int sm[512];
    int t = threadIdx.x;
    int v = (t < 391) ? g_bsum[t] : 0;
    sm[t] = v;
    __syncthreads();
    for (int d = 1; d < 512; d <<= 1) {
        int x = (t >= d) ? sm[t - d] : 0;
        __syncthreads();
        sm[t] += x;
        __syncthreads();
    }
    if (t < 391) g_bsum[t] = sm[t] - v;    // exclusive block offsets
    if (t == 511) g_rowptr[NN] = sm[511];  // total == EE
}

__global__ void k_scan3() {
    int i = blockIdx.x * 256 + threadIdx.x;
    if (i < NN) {
        g_rowptr[i] += g_bsum[blockIdx.x];
        g_cursor[i] = 0;
    }
}

__global__ void k_scatter(const int* __restrict__ ei) {
    int e = blockIdx.x * 256 + threadIdx.x;
    if (e < EE) {
        int d = ei[EE + e];
        int p = g_rowptr[d] + atomicAdd(&g_cursor[d], 1);
        g_col[p] = ei[e];
    }
}

// ---------------- fused GEMM (h = relu(in+b_prev) @ W) + attention-logit epilogue ----------------
// Also block-reduces the per-head max of als into g_gmax[layer*4 + h].
template <int K, int C, bool RELU_IN, int LAYER>
__global__ __launch_bounds__(128) void k_gemm(const float* __restrict__ in_ext,
                                              const float* __restrict__ W,
                                              const float* __restrict__ asrc,
                                              const float* __restrict__ adst,
                                              const float* __restrict__ bin) {
    constexpr int OC = C / 4;  // channels per head
    __shared__ float4 sW4[K * C / 4];
    __shared__ float sIn[8][132];
    __shared__ float sB[K > 0 ? K : 1];
    __shared__ float sA[C];
    __shared__ float sD[C];
    __shared__ unsigned sMax[4];
    float* sW = (float*)sW4;

    const float* in = RELU_IN ? (const float*)g_a4 : in_ext;
    int t = threadIdx.x;
    for (int i = t; i < K * C; i += 128) sW[i] = W[i];
    for (int i = t; i < C; i += 128) { sA[i] = asrc[i]; sD[i] = adst[i]; }
    if (RELU_IN) {
        for (int i = t; i < K; i += 128) sB[i] = bin[i];
    }
    if (t < 4) sMax[t] = 0u;
    __syncthreads();

    int row = blockIdx.x * 128 + t;
    float acc[C];
#pragma unroll
    for (int c = 0; c < C; c++) acc[c] = 0.f;

    for (int k0 = 0; k0 < K; k0 += 8) {
#pragma unroll
        for (int i = 0; i < 8; i++) {
            int idx = i * 128 + t;
            int r = idx >> 3;
            int kk = idx & 7;
            int gr = blockIdx.x * 128 + r;
            float v = 0.f;
            if (gr < NN) {
                v = in[gr * K + k0 + kk];
                if (RELU_IN) v = fmaxf(v + sB[k0 + kk], 0.f);
            }
            sIn[kk][r] = v;
        }
        __syncthreads();
#pragma unroll
        for (int kk = 0; kk < 8; kk++) {
            float a = sIn[kk][t];
            const float4* wr = &sW4[(k0 + kk) * (C / 4)];
#pragma unroll
            for (int c4 = 0; c4 < C / 4; c4++) {
                float4 w = wr[c4];
                acc[c4 * 4 + 0] += a * w.x;
                acc[c4 * 4 + 1] += a * w.y;
                acc[c4 * 4 + 2] += a * w.z;
                acc[c4 * 4 + 3] += a * w.w;
            }
        }
        __syncthreads();
    }

    float4 so;
    so.x = -1e30f; so.y = -1e30f; so.z = -1e30f; so.w = -1e30f;
    if (row < NN) {
#pragma unroll
        for (int c4 = 0; c4 < C / 4; c4++) {
            float4 o;
            o.x = acc[c4 * 4 + 0];
            o.y = acc[c4 * 4 + 1];
            o.z = acc[c4 * 4 + 2];
            o.w = acc[c4 * 4 + 3];
            g_h4[row * (C / 4) + c4] = o;
        }
        float4 dto;
#pragma unroll
        for (int hh = 0; hh < 4; hh++) {
            float s = 0.f, d = 0.f;
#pragma unroll
            for (int j = 0; j < OC; j++) {
                s += acc[hh * OC + j] * sA[hh * OC + j];
                d += acc[hh * OC + j] * sD[hh * OC + j];
            }
            ((float*)&so)[hh] = s;
            ((float*)&dto)[hh] = d;
        }
        g_als4[row] = so;
        g_ald4[row] = dto;
    }

    // per-head global max of als (warp shfl reduce -> smem atomic -> global atomic)
#pragma unroll
    for (int d = 16; d; d >>= 1) {
        so.x = fmaxf(so.x, __shfl_xor_sync(0xffffffffu, so.x, d));
        so.y = fmaxf(so.y, __shfl_xor_sync(0xffffffffu, so.y, d));
        so.z = fmaxf(so.z, __shfl_xor_sync(0xffffffffu, so.z, d));
        so.w = fmaxf(so.w, __shfl_xor_sync(0xffffffffu, so.w, d));
    }
    if ((t & 31) == 0) {
        atomicMax(&sMax[0], f2u_ord(so.x));
        atomicMax(&sMax[1], f2u_ord(so.y));
        atomicMax(&sMax[2], f2u_ord(so.z));
        atomicMax(&sMax[3], f2u_ord(so.w));
    }
    __syncthreads();
    if (t < 4) atomicMax(&g_gmax[LAYER * 4 + t], sMax[t]);
}

// ---------------- attention aggregation: warp per dst node, single-pass softmax ----------------
__device__ __forceinline__ float4 lrelu4(float4 v) {
    v.x = fmaxf(v.x, 0.2f * v.x);
    v.y = fmaxf(v.y, 0.2f * v.y);
    v.z = fmaxf(v.z, 0.2f * v.z);
    v.w = fmaxf(v.w, 0.2f * v.w);
    return v;
}
__device__ __forceinline__ float hsel(float4 v, int h) {
    return (h == 0) ? v.x : (h == 1) ? v.y : (h == 2) ? v.z : v.w;
}

template <int C, int OC, int LAYER>
__global__ __launch_bounds__(256) void k_agg() {
    __shared__ float4 sp[8][32];  // per-warp per-edge exp(e - m) for 4 heads
    int warp = threadIdx.x >> 5;
    int lane = threadIdx.x & 31;
    int n = blockIdx.x * 8 + warp;
    if (n >= NN) return;

    const float*  gh  = (const float*)g_h4;
    const float2* gh2 = (const float2*)g_h4;

    int c0, head;
    if (C == 64) { c0 = lane * 2; head = lane >> 3; }
    else { c0 = (lane < C) ? lane : 0; head = c0 / OC; }

    float4 ald4 = g_ald4[n];
    float4 asn  = g_als4[n];
    float4 es4;
    es4.x = asn.x + ald4.x; es4.y = asn.y + ald4.y;
    es4.z = asn.z + ald4.z; es4.w = asn.w + ald4.w;
    es4 = lrelu4(es4);

    // m >= every incoming edge logit of this dst: lrelu(gmax_als + ald) (lrelu monotone)
    float4 m4;
    m4.x = u2f_ord(g_gmax[LAYER * 4 + 0]) + ald4.x;
    m4.y = u2f_ord(g_gmax[LAYER * 4 + 1]) + ald4.y;
    m4.z = u2f_ord(g_gmax[LAYER * 4 + 2]) + ald4.z;
    m4.w = u2f_ord(g_gmax[LAYER * 4 + 3]) + ald4.w;
    m4 = lrelu4(m4);

    int start = g_rowptr[n];
    int end = g_rowptr[n + 1];

    // self-loop contribution
    float4 ps4;
    ps4.x = __expf(es4.x - m4.x);
    ps4.y = __expf(es4.y - m4.y);
    ps4.z = __expf(es4.z - m4.z);
    ps4.w = __expf(es4.w - m4.w);
    float ps = hsel(ps4, head);
    float4 s4;
    if (lane == 0) s4 = ps4;
    else { s4.x = 0.f; s4.y = 0.f; s4.z = 0.f; s4.w = 0.f; }

    float accx, accy = 0.f;
    if (C == 64) {
        float2 hv = gh2[n * 32 + lane];
        accx = ps * hv.x;
        accy = ps * hv.y;
    } else {
        accx = ps * gh[n * C + c0];
    }

    // single pass: exp + sum (edge-parallel) fused with channel-parallel gather
    for (int j0 = start; j0 < end; j0 += 32) {
        int lj = j0 + lane;
        bool vld = lj < end;
        int src = vld ? g_col[lj] : 0;
        float4 a4 = g_als4[src];
        float4 e4;
        e4.x = a4.x + ald4.x; e4.y = a4.y + ald4.y;
        e4.z = a4.z + ald4.z; e4.w = a4.w + ald4.w;
        e4 = lrelu4(e4);
        float4 p4;
        p4.x = vld ? __expf(e4.x - m4.x) : 0.f;
        p4.y = vld ? __expf(e4.y - m4.y) : 0.f;
        p4.z = vld ? __expf(e4.z - m4.z) : 0.f;
        p4.w = vld ? __expf(e4.w - m4.w) : 0.f;
        s4.x += p4.x; s4.y += p4.y; s4.z += p4.z; s4.w += p4.w;
        sp[warp][lane] = p4;
        __syncwarp();

        int cnt = min(32, end - j0);
        const float* pw = (const float*)&sp[warp][0];
        int jj = 0;
        for (; jj + 8 <= cnt; jj += 8) {
            int ss[8];
            float pp[8];
#pragma unroll
            for (int q = 0; q < 8; q++) {
                ss[q] = __shfl_sync(0xffffffffu, src, jj + q);
                pp[q] = pw[(jj + q) * 4 + head];
            }
            if (C == 64) {
                float2 hv[8];
#pragma unroll
                for (int q = 0; q < 8; q++) hv[q] = gh2[ss[q] * 32 + lane];
#pragma unroll
                for (int q = 0; q < 8; q++) { accx += pp[q] * hv[q].x; accy += pp[q] * hv[q].y; }
            } else {
                float hv[8];
#pragma unroll
                for (int q = 0; q < 8; q++) hv[q] = gh[ss[q] * C + c0];
#pragma unroll
                for (int q = 0; q < 8; q++) accx += pp[q] * hv[q];
            }
        }
        for (; jj < cnt; jj++) {
            int s0 = __shfl_sync(0xffffffffu, src, jj);
            float p0 = pw[jj * 4 + head];
            if (C == 64) {
                float2 h0 = gh2[s0 * 32 + lane];
                accx += p0 * h0.x;
                accy += p0 * h0.y;
            } else {
                accx += p0 * gh[s0 * C + c0];
            }
        }
        __syncwarp();
    }

#pragma unroll
    for (int d = 16; d; d >>= 1) {
        s4.x += __shfl_xor_sync(0xffffffffu, s4.x, d);
        s4.y += __shfl_xor_sync(0xffffffffu, s4.y, d);
        s4.z += __shfl_xor_sync(0xffffffffu, s4.z, d);
        s4.w += __shfl_xor_sync(0xffffffffu, s4.w, d);
    }
    float inv = 1.0f / hsel(s4, head);

    if (C == 64) {
        float2 o;
        o.x = accx * inv;
        o.y = accy * inv;
        ((float2*)g_a4)[n * 32 + lane] = o;
    } else if (lane < C) {
        ((float*)g_a4)[n * C + c0] = accx * inv;
    }
}

// ---------------- pooling + FC ----------------
__global__ void k_zero_pool() {
    int t = threadIdx.x;
    if (t < 512) g_pool[t] = 0.f;
    if (t < 64) g_cnt[t] = 0.f;
}

__global__ void k_pool(const int* __restrict__ batch, const float* __restrict__ b4) {
    int nn = blockIdx.x * 256 + threadIdx.x;
    if (nn >= NN) return;
    const float* ga = (const float*)g_a4;
    int b = batch[nn];
    atomicAdd(&g_cnt[b], 1.0f);
#pragma unroll
    for (int c = 0; c < 8; c++) {
        float v = fmaxf(ga[nn * 8 + c] + b4[c], 0.f);
        atomicAdd(&g_pool[b * 8 + c], v);
    }
}

__global__ void k_fc(const float* __restrict__ Wfc, const float* __restrict__ bfc,
                     float* __restrict__ out) {
    int id = blockIdx.x * 256 + threadIdx.x;
    if (id >= 64 * 32) return;
    int b = id >> 5;
    int o = id & 31;
    float invc = 1.0f / fmaxf(g_cnt[b], 1.0f);
    float acc = bfc[o];
#pragma unroll
    for (int c = 0; c < 8; c++) acc += (g_pool[b * 8 + c] * invc) * Wfc[c * 32 + o];
    out[id] = acc;
}

// ---------------- launch ----------------
extern "C" void kernel_launch(void* const* d_in, const int* in_sizes, int n_in,
                              void* d_out, int out_size) {
    const float* x     = (const float*)d_in[0];
    const int*   ei    = (const int*)d_in[1];     // int32 edge_index [2, E]
    const int*   batch = (const int*)d_in[2];     // int32 batch [N]
    const float* W1  = (const float*)d_in[3];
    const float* as1 = (const float*)d_in[4];
    const float* ad1 = (const float*)d_in[5];
    const float* b1  = (const float*)d_in[6];
    const float* W2  = (const float*)d_in[7];
    const float* as2 = (const float*)d_in[8];
    const float* ad2 = (const float*)d_in[9];
    const float* b2  = (const float*)d_in[10];
    const float* W3  = (const float*)d_in[11];
    const float* as3 = (const float*)d_in[12];
    const float* ad3 = (const float*)d_in[13];
    const float* b3  = (const float*)d_in[14];
    const float* W4  = (const float*)d_in[15];
    const float* as4 = (const float*)d_in[16];
    const float* ad4 = (const float*)d_in[17];
    const float* b4  = (const float*)d_in[18];
    const float* Wfc = (const float*)d_in[19];
    const float* bfc = (const float*)d_in[20];

    const int NBLK = (NN + 255) / 256;   // 391
    const int EBLK = (EE + 255) / 256;   // 6250
    const int GBLK = (NN + 127) / 128;   // 782
    const int ABLK = (NN + 7) / 8;       // 12500

    // CSR by destination (shared by all 4 layers); gemm1 interleaved so it lands
    // at launch index 3 (the launch ncu's -s/-c window captures).
    k_zero_cursor<<<NBLK, 256>>>();
    k_count<<<EBLK, 256>>>(ei);
    k_scan1<<<NBLK, 256>>>();
    k_gemm<128, 64, false, 0><<<GBLK, 128>>>(x, W1, as1, ad1, nullptr);  // independent of CSR
    k_scan2<<<1, 512>>>();
    k_scan3<<<NBLK, 256>>>();
    k_scatter<<<EBLK, 256>>>(ei);

    // layer 1: 128 -> 4x16 (gemm already issued above)
    k_agg<64, 16, 0><<<ABLK, 256>>>();
    // layer 2: 64 -> 4x8  (relu(prev + b1) fused into GEMM load)
    k_gemm<64, 32, true, 1><<<GBLK, 128>>>(nullptr, W2, as2, ad2, b1);
    k_agg<32, 8, 1><<<ABLK, 256>>>();
    // layer 3: 32 -> 4x4
    k_gemm<32, 16, true, 2><<<GBLK, 128>>>(nullptr, W3, as3, ad3, b2);
    k_agg<16, 4, 2><<<ABLK, 256>>>();
    // layer 4: 16 -> 4x2
    k_gemm<16, 8, true, 3><<<GBLK, 128>>>(nullptr, W4, as4, ad4, b3);
    k_agg<8, 2, 3><<<ABLK, 256>>>();

    // global mean pool (relu(prev + b4)) + FC
    k_zero_pool<<<1, 512>>>();
    k_pool<<<NBLK, 256>>>(batch, b4);
    k_fc<<<8, 256>>>(Wfc, bfc, (float*)d_out);
}

// round 10
// speedup vs baseline: 1.0440x; 1.0440x over previous
#include <cuda_runtime.h>
#include <math.h>

#define NN 100000
#define EE 1600000

// ---------------- static device scratch (no allocation allowed) ----------------
__device__ float4   g_h4[NN * 16];    // per-layer transformed features (row stride C floats)
__device__ float4   g_a4[NN * 16];    // aggregation output (next layer input, pre-bias)
__device__ float4   g_als4[NN];       // attention logits (src side), one float4 = 4 heads
__device__ float4   g_ald4[NN];       // attention logits (dst side)
__device__ int      g_rowptr[NN + 1];
__device__ int      g_cursor[NN];
__device__ int      g_col[EE];
__device__ int      g_bsum[512];
__device__ unsigned g_gmax[16];       // per-layer (4) x per-head (4) global max of als, order-encoded
__device__ float    g_pool[64 * 8];
__device__ float    g_cnt[64];

// order-preserving float<->uint encoding (works across signs)
__device__ __forceinline__ unsigned f2u_ord(float x) {
    unsigned s = __float_as_uint(x);
    return (s & 0x80000000u) ? ~s : (s | 0x80000000u);
}
__device__ __forceinline__ float u2f_ord(unsigned u) {
    unsigned s = (u & 0x80000000u) ? (u ^ 0x80000000u) : ~u;
    return __uint_as_float(s);
}

// ---------------- CSR build ----------------
__global__ void k_zero_cursor() {
    int i = blockIdx.x * 256 + threadIdx.x;
    if (i < NN) g_cursor[i] = 0;
    if (blockIdx.x == 0 && threadIdx.x < 16) g_gmax[threadIdx.x] = 0u;
}

__global__ void k_count(const int* __restrict__ ei) {
    int e = blockIdx.x * 256 + threadIdx.x;
    if (e < EE) atomicAdd(&g_cursor[ei[EE + e]], 1);
}

__global__ void k_scan1() {
    __shared__ int sm[256];
    int t = threadIdx.x;
    int i = blockIdx.x * 256 + t;
    int v = (i < NN) ? g_cursor[i] : 0;
    sm[t] = v;
    __syncthreads();
    for (int d = 1; d < 256; d <<= 1) {
        int x = (t >= d) ? sm[t - d] : 0;
        __syncthreads();
        sm[t] += x;
        __syncthreads();
    }
    if (i < NN) g_rowptr[i] = sm[t] - v;
    if (t == 255) g_bsum[blockIdx.x] = sm[255];
}

__global__ void k_scan2() {
    __shared__ int sm[512];
    int t = threadIdx.x;
    int v = (t < 391) ? g_bsum[t] : 0;
    sm[t] = v;
    __syncthreads();
    for (int d = 1; d < 512; d <<= 1) {
        int x = (t >= d) ? sm[t - d] : 0;
        __syncthreads();
        sm[t] += x;
        __syncthreads();
    }
    if (t < 391) g_bsum[t] = sm[t] - v;
    if (t == 511) g_rowptr[NN] = sm[511];
}

__global__ void k_scan3() {
    int i = blockIdx.x * 256 + threadIdx.x;
    if (i < NN) {
        g_rowptr[i] += g_bsum[blockIdx.x];
        g_cursor[i] = 0;
    }
}

__global__ void k_scatter(const int* __restrict__ ei) {
    int e = blockIdx.x * 256 + threadIdx.x;
    if (e < EE) {
        int d = ei[EE + e];
        int p = g_rowptr[d] + atomicAdd(&g_cursor[d], 1);
        g_col[p] = ei[e];
    }
}

// ---------------- register-blocked GEMM + attention-logit epilogue ----------------
// Block: 128 rows x C cols, 256 threads, BK=16. Thread tile TM x TN.
template <int K, int C, bool RELU_IN, int LAYER>
__global__ __launch_bounds__(256) void k_gemm(const float* __restrict__ in_ext,
                                              const float* __restrict__ W,
                                              const float* __restrict__ asrc,
                                              const float* __restrict__ adst,
                                              const float* __restrict__ bin) {
    constexpr int OC = C / 4;                 // channels per head
    constexpr int TX = (C < 16) ? C : 16;     // threads along cols
    constexpr int TN = C / TX;                // cols per thread
    constexpr int TY = 256 / TX;              // threads along rows
    constexpr int TM = 128 / TY;              // rows per thread
    constexpr int GSZ = OC / TN;              // lanes covering one head

    __shared__ float sIn[16][132];            // [k][row], padded (132*4B = 33*16B keeps rows 16B-aligned)
    __shared__ float4 sW4[16 * (C / 4)];      // [k][col/4]
    __shared__ float sB[K];
    __shared__ float sA[C];
    __shared__ float sD[C];
    __shared__ unsigned sMax[4];

    const float* in = RELU_IN ? (const float*)g_a4 : in_ext;
    int t = threadIdx.x;
    int tx = t % TX;
    int ty = t / TX;

    for (int i = t; i < C; i += 256) { sA[i] = asrc[i]; sD[i] = adst[i]; }
    if (RELU_IN) {
        for (int i = t; i < K; i += 256) sB[i] = bin[i];
    }
    if (t < 4) sMax[t] = 0u;
    __syncthreads();   // sB is read by ALL threads in the staging loop below (R9 bug fix)

    float acc[TM][TN];
#pragma unroll
    for (int i = 0; i < TM; i++)
#pragma unroll
        for (int j = 0; j < TN; j++) acc[i][j] = 0.f;

    int rowbase = blockIdx.x * 128;

    for (int k0 = 0; k0 < K; k0 += 16) {
        // stage A tile (transpose to [k][row])
#pragma unroll
        for (int j = 0; j < 2; j++) {
            int i = t + j * 256;             // 0..511
            int q = i & 3;                   // k-subchunk (4 floats)
            int r = i >> 2;                  // row 0..127
            int gr = rowbase + r;
            float4 v = make_float4(0.f, 0.f, 0.f, 0.f);
            if (gr < NN) {
                v = *(const float4*)(in + gr * K + k0 + q * 4);
                if (RELU_IN) {
                    v.x = fmaxf(v.x + sB[k0 + q * 4 + 0], 0.f);
                    v.y = fmaxf(v.y + sB[k0 + q * 4 + 1], 0.f);
                    v.z = fmaxf(v.z + sB[k0 + q * 4 + 2], 0.f);
                    v.w = fmaxf(v.w + sB[k0 + q * 4 + 3], 0.f);
                }
            }
            sIn[q * 4 + 0][r] = v.x;
            sIn[q * 4 + 1][r] = v.y;
            sIn[q * 4 + 2][r] = v.z;
            sIn[q * 4 + 3][r] = v.w;
        }
        // stage W tile
        if (t < 4 * C) {
            int kr = t / (C / 4);
            int cq = t % (C / 4);
            sW4[kr * (C / 4) + cq] = *(const float4*)(W + (k0 + kr) * C + cq * 4);
        }
        __syncthreads();

#pragma unroll
        for (int kk = 0; kk < 16; kk++) {
            float a[TM];
            {
                float4 a0 = *(const float4*)&sIn[kk][ty * TM];
                a[0] = a0.x; a[1] = a0.y; a[2] = a0.z; a[3] = a0.w;
                if (TM == 8) {
                    float4 a1 = *(const float4*)&sIn[kk][ty * TM + 4];
                    a[4] = a1.x; a[5] = a1.y; a[6] = a1.z; a[7] = a1.w;
                }
            }
            float w[TN];
            if (TN == 4) {
                float4 wv = sW4[kk * (C / 4) + tx];
                w[0] = wv.x; w[1] = wv.y; w[2] = wv.z; w[3] = wv.w;
            } else if (TN == 2) {
                float2 wv = ((const float2*)sW4)[kk * (C / 2) + tx];
                w[0] = wv.x; w[1] = wv.y;
            } else {
                w[0] = ((const float*)sW4)[kk * C + tx];
            }
#pragma unroll
            for (int i = 0; i < TM; i++)
#pragma unroll
                for (int j = 0; j < TN; j++) acc[i][j] += a[i] * w[j];
        }
        __syncthreads();
    }

    // epilogue: write h, per-head attention logits, global max of als
    int head = (tx * TN) / OC;
    float smax_local = -1e30f;
    float* galf = (float*)g_als4;
    float* gadf = (float*)g_ald4;
#pragma unroll
    for (int i = 0; i < TM; i++) {
        int gr = rowbase + ty * TM + i;
        bool vld = gr < NN;
        if (vld) {
            if (TN == 4) {
                float4 o = make_float4(acc[i][0], acc[i][1], acc[i][2], acc[i][3]);
                g_h4[gr * (C / 4) + tx] = o;
            } else if (TN == 2) {
                float2 o = make_float2(acc[i][0], acc[i][1]);
                ((float2*)g_h4)[gr * (C / 2) + tx] = o;
            } else {
                ((float*)g_h4)[gr * C + tx] = acc[i][0];
            }
        }
        float s = 0.f, d = 0.f;
#pragma unroll
        for (int j = 0; j < TN; j++) {
            s += acc[i][j] * sA[tx * TN + j];
            d += acc[i][j] * sD[tx * TN + j];
        }
#pragma unroll
        for (int dd = 1; dd < GSZ; dd <<= 1) {
            s += __shfl_xor_sync(0xffffffffu, s, dd);
            d += __shfl_xor_sync(0xffffffffu, d, dd);
        }
        if (vld && (tx % GSZ) == 0) {
            galf[gr * 4 + head] = s;
            gadf[gr * 4 + head] = d;
        }
        smax_local = fmaxf(smax_local, vld ? s : -1e30f);
    }
    if ((tx % GSZ) == 0) atomicMax(&sMax[head], f2u_ord(smax_local));
    __syncthreads();
    if (t < 4) atomicMax(&g_gmax[LAYER * 4 + t], sMax[t]);
}

// ---------------- attention aggregation ----------------
__device__ __forceinline__ float4 lrelu4(float4 v) {
    v.x = fmaxf(v.x, 0.2f * v.x);
    v.y = fmaxf(v.y, 0.2f * v.y);
    v.z = fmaxf(v.z, 0.2f * v.z);
    v.w = fmaxf(v.w, 0.2f * v.w);
    return v;
}
__device__ __forceinline__ float hsel(float4 v, int h) {
    return (h == 0) ? v.x : (h == 1) ? v.y : (h == 2) ? v.z : v.w;
}

// Warp per dst node. Edge-parallel exp into smem, then vectorized gather:
// each edge occupies L = C/VEC lanes; EPI = 32/L edges per iteration, batched 4x.
template <int C, int OC, int VEC, int LAYER>
__global__ __launch_bounds__(256) void k_agg() {
    constexpr int L = C / VEC;
    constexpr int EPI = 32 / L;
    __shared__ float4 sp4[8][32];   // exp(e-m) for 4 heads, per edge slot

    int warp = threadIdx.x >> 5;
    int lane = threadIdx.x & 31;
    int n = blockIdx.x * 8 + warp;
    if (n >= NN) return;

    int slot = lane / L;
    int lpos = lane % L;
    int ch0 = lpos * VEC;
    int head = ch0 / OC;

    const float* ghf = (const float*)g_h4;

    float4 ald4 = g_ald4[n];
    float4 asn  = g_als4[n];
    float4 es4;
    es4.x = asn.x + ald4.x; es4.y = asn.y + ald4.y;
    es4.z = asn.z + ald4.z; es4.w = asn.w + ald4.w;
    es4 = lrelu4(es4);

    float4 m4;
    m4.x = u2f_ord(g_gmax[LAYER * 4 + 0]) + ald4.x;
    m4.y = u2f_ord(g_gmax[LAYER * 4 + 1]) + ald4.y;
    m4.z = u2f_ord(g_gmax[LAYER * 4 + 2]) + ald4.z;
    m4.w = u2f_ord(g_gmax[LAYER * 4 + 3]) + ald4.w;
    m4 = lrelu4(m4);

    float4 ps4;
    ps4.x = __expf(es4.x - m4.x);
    ps4.y = __expf(es4.y - m4.y);
    ps4.z = __expf(es4.z - m4.z);
    ps4.w = __expf(es4.w - m4.w);
    float ps = hsel(ps4, head);

    // self-loop contribution (slot 0 only, to avoid duplication)
    float acc[VEC];
    float accs;
    {
        float hv[VEC];
        if (VEC == 4) {
            float4 h4 = *(const float4*)(ghf + n * C + ch0);
            hv[0] = h4.x; hv[1] = h4.y; hv[2] = h4.z; hv[3] = h4.w;
        } else {
            float2 h2 = *(const float2*)(ghf + n * C + ch0);
            hv[0] = h2.x; hv[1] = h2.y;
        }
        float psel = (slot == 0) ? ps : 0.f;
#pragma unroll
        for (int v = 0; v < VEC; v++) acc[v] = psel * hv[v];
        accs = psel;
    }

    int start = g_rowptr[n];
    int end = g_rowptr[n + 1];

    for (int j0 = start; j0 < end; j0 += 32) {
        int lj = j0 + lane;
        bool vld = lj < end;
        int src = vld ? g_col[lj] : 0;
        float4 a4 = g_als4[src];
        float4 e4;
        e4.x = a4.x + ald4.x; e4.y = a4.y + ald4.y;
        e4.z = a4.z + ald4.z; e4.w = a4.w + ald4.w;
        e4 = lrelu4(e4);
        float4 p4;
        p4.x = vld ? __expf(e4.x - m4.x) : 0.f;
        p4.y = vld ? __expf(e4.y - m4.y) : 0.f;
        p4.z = vld ? __expf(e4.z - m4.z) : 0.f;
        p4.w = vld ? __expf(e4.w - m4.w) : 0.f;
        sp4[warp][lane] = p4;
        __syncwarp();

        int cnt = min(32, end - j0);
        const float* pw = (const float*)&sp4[warp][0];
        // batches of 4 iterations (4*EPI edges), loads batched for MLP
        for (int jj = 0; jj < cnt; jj += 4 * EPI) {
            int e0 = jj + slot;
            int s0 = __shfl_sync(0xffffffffu, src, e0);
            int s1 = __shfl_sync(0xffffffffu, src, e0 + EPI);
            int s2 = __shfl_sync(0xffffffffu, src, e0 + 2 * EPI);
            int s3 = __shfl_sync(0xffffffffu, src, e0 + 3 * EPI);
            float p0 = pw[e0 * 4 + head];
            float p1 = pw[(e0 + EPI) * 4 + head];
            float p2 = pw[(e0 + 2 * EPI) * 4 + head];
            float p3 = pw[(e0 + 3 * EPI) * 4 + head];
            if (VEC == 4) {
                float4 h0 = *(const float4*)(ghf + s0 * C + ch0);
                float4 h1 = *(const float4*)(ghf + s1 * C + ch0);
                float4 h2 = *(const float4*)(ghf + s2 * C + ch0);
                float4 h3 = *(const float4*)(ghf + s3 * C + ch0);
                acc[0] += p0 * h0.x; acc[1] += p0 * h0.y; acc[2] += p0 * h0.z; acc[3] += p0 * h0.w;
                acc[0] += p1 * h1.x; acc[1] += p1 * h1.y; acc[2] += p1 * h1.z; acc[3] += p1 * h1.w;
                acc[0] += p2 * h2.x; acc[1] += p2 * h2.y; acc[2] += p2 * h2.z; acc[3] += p2 * h2.w;
                acc[0] += p3 * h3.x; acc[1] += p3 * h3.y; acc[2] += p3 * h3.z; acc[3] += p3 * h3.w;
            } else {
                float2 h0 = *(const float2*)(ghf + s0 * C + ch0);
                float2 h1 = *(const float2*)(ghf + s1 * C + ch0);
                float2 h2 = *(const float2*)(ghf + s2 * C + ch0);
                float2 h3 = *(const float2*)(ghf + s3 * C + ch0);
                acc[0] += p0 * h0.x; acc[1] += p0 * h0.y;
                acc[0] += p1 * h1.x; acc[1] += p1 * h1.y;
                acc[0] += p2 * h2.x; acc[1] += p2 * h2.y;
                acc[0] += p3 * h3.x; acc[1] += p3 * h3.y;
            }
            accs += p0 + p1 + p2 + p3;
        }
        __syncwarp();
    }

    // fold across edge slots (lanes with same channel group)
#pragma unroll
    for (int d = L; d < 32; d <<= 1) {
#pragma unroll
        for (int v = 0; v < VEC; v++) acc[v] += __shfl_xor_sync(0xffffffffu, acc[v], d);
        accs += __shfl_xor_sync(0xffffffffu, accs, d);
    }

    float inv = __fdividef(1.0f, accs + 1e-16f);
    if (slot == 0) {
        float* gaf = (float*)g_a4;
        if (VEC == 4) {
            float4 o = make_float4(acc[0] * inv, acc[1] * inv, acc[2] * inv, acc[3] * inv);
            *(float4*)(gaf + n * C + ch0) = o;
        } else {
            float2 o = make_float2(acc[0] * inv, acc[1] * inv);
            *(float2*)(gaf + n * C + ch0) = o;
        }
    }
}

// ---------------- pooling + FC ----------------
__global__ void k_zero_pool() {
    int t = threadIdx.x;
    if (t < 512) g_pool[t] = 0.f;
    if (t < 64) g_cnt[t] = 0.f;
}

__global__ void k_pool(const int* __restrict__ batch, const float* __restrict__ b4) {
    int nn = blockIdx.x * 256 + threadIdx.x;
    if (nn >= NN) return;
    const float* ga = (const float*)g_a4;
    int b = batch[nn];
    atomicAdd(&g_cnt[b], 1.0f);
#pragma unroll
    for (int c = 0; c < 8; c++) {
        float v = fmaxf(ga[nn * 8 + c] + b4[c], 0.f);
        atomicAdd(&g_pool[b * 8 + c], v);
    }
}

__global__ void k_fc(const float* __restrict__ Wfc, const float* __restrict__ bfc,
                     float* __restrict__ out) {
    int id = blockIdx.x * 256 + threadIdx.x;
    if (id >= 64 * 32) return;
    int b = id >> 5;
    int o = id & 31;
    float invc = 1.0f / fmaxf(g_cnt[b], 1.0f);
    float acc = bfc[o];
#pragma unroll
    for (int c = 0; c < 8; c++) acc += (g_pool[b * 8 + c] * invc) * Wfc[c * 32 + o];
    out[id] = acc;
}

// ---------------- launch ----------------
extern "C" void kernel_launch(void* const* d_in, const int* in_sizes, int n_in,
                              void* d_out, int out_size) {
    const float* x     = (const float*)d_in[0];
    const int*   ei    = (const int*)d_in[1];
    const int*   batch = (const int*)d_in[2];
    const float* W1  = (const float*)d_in[3];
    const float* as1 = (const float*)d_in[4];
    const float* ad1 = (const float*)d_in[5];
    const float* b1  = (const float*)d_in[6];
    const float* W2  = (const float*)d_in[7];
    const float* as2 = (const float*)d_in[8];
    const float* ad2 = (const float*)d_in[9];
    const float* b2  = (const float*)d_in[10];
    const float* W3  = (const float*)d_in[11];
    const float* as3 = (const float*)d_in[12];
    const float* ad3 = (const float*)d_in[13];
    const float* b3  = (const float*)d_in[14];
    const float* W4  = (const float*)d_in[15];
    const float* as4 = (const float*)d_in[16];
    const float* ad4 = (const float*)d_in[17];
    const float* b4  = (const float*)d_in[18];
    const float* Wfc = (const float*)d_in[19];
    const float* bfc = (const float*)d_in[20];

    const int NBLK = (NN + 255) / 256;   // 391
    const int EBLK = (EE + 255) / 256;   // 6250
    const int GBLK = (NN + 127) / 128;   // 782
    const int ABLK = (NN + 7) / 8;       // 12500

    // CSR build; gemm1 kept at 4th launch (the slot ncu captures) for A/B.
    k_zero_cursor<<<NBLK, 256>>>();
    k_count<<<EBLK, 256>>>(ei);
    k_scan1<<<NBLK, 256>>>();
    k_gemm<128, 64, false, 0><<<GBLK, 256>>>(x, W1, as1, ad1, nullptr);
    k_scan2<<<1, 512>>>();
    k_scan3<<<NBLK, 256>>>();
    k_scatter<<<EBLK, 256>>>(ei);

    // layer 1: 128 -> 4x16
    k_agg<64, 16, 4, 0><<<ABLK, 256>>>();
    // layer 2: 64 -> 4x8
    k_gemm<64, 32, true, 1><<<GBLK, 256>>>(nullptr, W2, as2, ad2, b1);
    k_agg<32, 8, 4, 1><<<ABLK, 256>>>();
    // layer 3: 32 -> 4x4
    k_gemm<32, 16, true, 2><<<GBLK, 256>>>(nullptr, W3, as3, ad3, b2);
    k_agg<16, 4, 4, 2><<<ABLK, 256>>>();
    // layer 4: 16 -> 4x2
    k_gemm<16, 8, true, 3><<<GBLK, 256>>>(nullptr, W4, as4, ad4, b3);
    k_agg<8, 2, 2, 3><<<ABLK, 256>>>();

    // global mean pool + FC
    k_zero_pool<<<1, 512>>>();
    k_pool<<<NBLK, 256>>>(batch, b4);
    k_fc<<<8, 256>>>(Wfc, bfc, (float*)d_out);
}